// round 15
// baseline (speedup 1.0000x reference)
#include <cuda_runtime.h>
#include <math.h>

#define B_ROWS   2048
#define NL       64
#define NN       16
#define NO       2048
#define ZSTRIDE  80          // NL + NN
#define TILE_B   64
#define CHUNK_O  128         // A-chunk staged in smem
#define TILE_O   256         // per-block o coverage (2 chunks)
#define NYBLK    (NO / TILE_O)   // 8 blocks cover one row
#define MAX_TILES 48
#define NTHREADS 256

// ---------------- device scratch (no allocations allowed) ----------------
__device__ int   g_nid[B_ROWS];
__device__ int   g_order[B_ROWS];
__device__ int   g_bucket_base[NN + 1];
__device__ int   g_tile_bucket[MAX_TILES];
__device__ int   g_tile_start[MAX_TILES];
__device__ int   g_tile_cnt[MAX_TILES];
__device__ int   g_num_tiles;
__device__ float g_rowsum[B_ROWS];   // per-row sum of exp(logit)
__device__ int   g_done[B_ROWS];     // per-row completed-block counter

// ---------------- packed f32x2 helpers (sm_103a FFMA2 via PTX) ------------
__device__ __forceinline__ void ffma2(unsigned long long& acc,
                                      unsigned long long a,
                                      unsigned long long b)
{
    asm("fma.rn.f32x2 %0, %1, %2, %0;" : "+l"(acc) : "l"(a), "l"(b));
}
__device__ __forceinline__ unsigned long long bcast2(float v)
{
    unsigned long long r;
    asm("mov.b64 %0, {%1, %1};" : "=l"(r) : "f"(v));
    return r;
}
__device__ __forceinline__ float2 unpack2(unsigned long long p)
{
    float2 f;
    asm("mov.b64 {%0, %1}, %2;" : "=f"(f.x), "=f"(f.y) : "l"(p));
    return f;
}

// ---------------- kernel 1: argmax + theta + reset row state --------------
__global__ void k_prep(const float* __restrict__ z,
                       const float* __restrict__ px_r,
                       float* __restrict__ theta_out)
{
    int g = blockIdx.x * blockDim.x + threadIdx.x;
    if (g < B_ROWS) {
        const float* p = z + (size_t)g * ZSTRIDE + NL;
        float best = p[0]; int bi = 0;
        #pragma unroll
        for (int i = 1; i < NN; i++) {
            float v = p[i];
            if (v > best) { best = v; bi = i; }   // first-max wins (jnp.argmax)
        }
        g_nid[g]    = bi;
        g_rowsum[g] = 0.f;
        g_done[g]   = 0;
    }
    if (g < NO) theta_out[g] = expf(px_r[g]);
}

// ---------------- kernel 2: counting sort by nid + tile list --------------
__global__ void k_sort()
{
    __shared__ int cnt[NN];
    __shared__ int offs[NN];
    int t = threadIdx.x;
    if (t < NN) cnt[t] = 0;
    __syncthreads();
    for (int b = t; b < B_ROWS; b += blockDim.x)
        atomicAdd(&cnt[g_nid[b]], 1);
    __syncthreads();
    if (t == 0) {
        int acc = 0;
        for (int i = 0; i < NN; i++) {
            g_bucket_base[i] = acc;
            offs[i] = acc;
            acc += cnt[i];
        }
        g_bucket_base[NN] = acc;
    }
    __syncthreads();
    for (int b = t; b < B_ROWS; b += blockDim.x) {
        int p = atomicAdd(&offs[g_nid[b]], 1);
        g_order[p] = b;
    }
    if (t == 0) {
        int nt = 0;
        for (int i = 0; i < NN; i++) {
            int base = g_bucket_base[i];
            int c    = g_bucket_base[i + 1] - base;
            for (int s = 0; s < c; s += TILE_B) {
                g_tile_bucket[nt] = i;
                g_tile_start[nt]  = base + s;
                g_tile_cnt[nt]    = min(TILE_B, c - s);
                nt++;
            }
        }
        g_num_tiles = nt;
    }
}

// Z tile swizzle: row-major [r][64], float4-group column c4 (0..15) XORed by
// a bit derived from r so that rows r and r+4 (the two ty-groups of a warp)
// land 16 banks apart. Mainloop loads are LDS.128, conflict-free.
__device__ __forceinline__ int zc4(int r, int c4)
{
    return c4 ^ (((r >> 2) & 1) << 2);
}

// ---------------- kernel 3: fully-fused GEMM + softmax --------------------
// Writes UNNORMALIZED exp(logit) straight into mu; accumulates per-row sums;
// the 8th (last) block to finish a row rescales it by sf/rowsum in-place.
// Unnormalized exp is overflow-safe here (|logit| <~ 41 << 88).
// Dynamic smem = 64*64 (Zs) + 64*128 (As) floats = 49152 B exactly.
__global__ __launch_bounds__(NTHREADS)
void k_gemm(const float* __restrict__ z,
            const float* __restrict__ W,
            const float* __restrict__ S,
            const float* __restrict__ offsets,
            const float* __restrict__ sf,
            float* __restrict__ mu)
{
    int tile = blockIdx.x;
    if (tile >= g_num_tiles) return;

    extern __shared__ float sm[];
    float* Zs = sm;                       // [64][64] row-major, swizzled c4
    float* As = sm + TILE_B * NL;         // [64][128]

    int tid    = threadIdx.x;
    int bucket = g_tile_bucket[tile];
    int start  = g_tile_start[tile];
    int vcnt   = g_tile_cnt[tile];

    int tx = tid & 15;     // col group: cols {tx*4..+3} and {64+tx*4..+3}
    int ty = tid >> 4;     // row group: rows ty*4..+3

    // row indices for this thread's 4 output rows (register-cached)
    int rowidx[4];
    #pragma unroll
    for (int i = 0; i < 4; i++) {
        int r = ty * 4 + i;
        rowidx[i] = (r < vcnt) ? g_order[start + r] : -1;
    }

    // ---- stage Z row-major swizzled (64 rows x 16 float4 = 1024 float4) ----
    {
        #pragma unroll
        for (int j = 0; j < 4; j++) {
            int e  = tid + j * NTHREADS;   // 0..1023
            int r  = e >> 4;
            int l4 = e & 15;
            int row = (r < vcnt) ? g_order[start + r] : -1;
            float4 v = make_float4(0.f, 0.f, 0.f, 0.f);
            if (row >= 0)
                v = *(const float4*)(z + (size_t)row * ZSTRIDE + l4 * 4);
            *(float4*)(Zs + r * NL + zc4(r, l4) * 4) = v;
        }
    }

    const float4* W4 = (const float4*)W;
    const float4* S4 = (const float4*)(S + (size_t)bucket * NL * NO);

    #pragma unroll
    for (int chunk = 0; chunk < TILE_O / CHUNK_O; chunk++) {
        int o0 = blockIdx.y * TILE_O + chunk * CHUNK_O;

        __syncthreads();   // Z stage done (chunk 0) / prior compute reads done

        // ---- stage A_eff = W + S[bucket] (64 x 128 floats = 2048 float4) --
        {
            int ob4 = o0 >> 2;
            #pragma unroll
            for (int j = 0; j < 8; j++) {
                int e  = tid + j * NTHREADS;   // 0..2047
                int k  = e >> 5;
                int c4 = e & 31;
                float4 w = W4[(size_t)k * (NO / 4) + ob4 + c4];
                float4 s = S4[(size_t)k * (NO / 4) + ob4 + c4];
                ((float4*)(As + k * CHUNK_O))[c4] =
                    make_float4(w.x + s.x, w.y + s.y, w.z + s.z, w.w + s.w);
            }
        }
        __syncthreads();

        // packed accumulators: acc[i][j] = (col 2j, col 2j+1) of group
        unsigned long long acc[4][8];
        #pragma unroll
        for (int i = 0; i < 4; i++)
            #pragma unroll
            for (int j = 0; j < 8; j++) acc[i][j] = 0ull;

        #pragma unroll 4
        for (int k4 = 0; k4 < NL; k4 += 4) {
            float4 zq[4];
            #pragma unroll
            for (int i = 0; i < 4; i++) {
                int r = ty * 4 + i;
                zq[i] = *(const float4*)(Zs + r * NL + zc4(r, k4 >> 2) * 4);
            }
            #pragma unroll
            for (int kk = 0; kk < 4; kk++) {
                ulonglong2 a0 = *(const ulonglong2*)(As + (k4 + kk) * CHUNK_O + tx * 4);
                ulonglong2 a1 = *(const ulonglong2*)(As + (k4 + kk) * CHUNK_O + 64 + tx * 4);
                #pragma unroll
                for (int i = 0; i < 4; i++) {
                    unsigned long long zz = bcast2((&zq[i].x)[kk]);
                    ffma2(acc[i][0], zz, a0.x);
                    ffma2(acc[i][1], zz, a0.y);
                    ffma2(acc[i][2], zz, a1.x);
                    ffma2(acc[i][3], zz, a1.y);
                }
            }
        }

        // ---- epilogue: exp(logit+off) -> mu, accumulate row sums ----------
        const float4 offlo = *(const float4*)(offsets + (size_t)bucket * NO + o0 + tx * 4);
        const float4 offhi = *(const float4*)(offsets + (size_t)bucket * NO + o0 + 64 + tx * 4);
        #pragma unroll
        for (int i = 0; i < 4; i++) {
            int row = rowidx[i];   // uniform across the 16-lane tx-group
            float2 p0 = unpack2(acc[i][0]);
            float2 p1 = unpack2(acc[i][1]);
            float2 p2 = unpack2(acc[i][2]);
            float2 p3 = unpack2(acc[i][3]);
            float4 elo = make_float4(__expf(p0.x + offlo.x), __expf(p0.y + offlo.y),
                                     __expf(p1.x + offlo.z), __expf(p1.y + offlo.w));
            float4 ehi = make_float4(__expf(p2.x + offhi.x), __expf(p2.y + offhi.y),
                                     __expf(p3.x + offhi.z), __expf(p3.y + offhi.w));
            float rs = 0.f;
            if (row >= 0) {
                float* dst = mu + (size_t)row * NO + o0;
                *(float4*)(dst + tx * 4)      = elo;
                *(float4*)(dst + 64 + tx * 4) = ehi;
                rs = ((elo.x + elo.y) + (elo.z + elo.w))
                   + ((ehi.x + ehi.y) + (ehi.z + ehi.w));
            }
            // reduce across the 16-lane tx-group
            rs += __shfl_xor_sync(0xffffffffu, rs, 8);
            rs += __shfl_xor_sync(0xffffffffu, rs, 4);
            rs += __shfl_xor_sync(0xffffffffu, rs, 2);
            rs += __shfl_xor_sync(0xffffffffu, rs, 1);
            if (tx == 0 && row >= 0)
                atomicAdd(&g_rowsum[row], rs);
        }
    }

    // ---- completion: 8th block to finish a row rescales it in place ------
    __threadfence();   // make this block's mu stores + rowsum adds visible
    #pragma unroll
    for (int i = 0; i < 4; i++) {
        int row = rowidx[i];
        int old = 0;
        if (tx == 0 && row >= 0)
            old = atomicAdd(&g_done[row], 1);
        old = __shfl_sync(0xffffffffu, old, 0, 16);
        if (row >= 0 && old == NYBLK - 1) {
            __threadfence();           // acquire: order reads after counter
            float total = 0.f;
            if (tx == 0) total = atomicAdd(&g_rowsum[row], 0.f);
            total = __shfl_sync(0xffffffffu, total, 0, 16);
            float scale = sf[row] / total;
            float4* rowp = (float4*)(mu + (size_t)row * NO);
            #pragma unroll 8
            for (int q = 0; q < 32; q++) {
                float4 v = __ldcg(&rowp[tx + q * 16]);
                rowp[tx + q * 16] = make_float4(v.x * scale, v.y * scale,
                                                v.z * scale, v.w * scale);
            }
        }
    }
}

// -------------------------------------------------------------------------
extern "C" void kernel_launch(void* const* d_in, const int* in_sizes, int n_in,
                              void* d_out, int out_size)
{
    const float* z       = (const float*)d_in[0];
    const float* sf      = (const float*)d_in[1];
    const float* W       = (const float*)d_in[2];
    const float* S       = (const float*)d_in[3];
    const float* offsets = (const float*)d_in[4];
    const float* px_r    = (const float*)d_in[5];
    float* out   = (float*)d_out;
    float* theta = out + (out_size - NO);   // layout: mu[B,NO] then theta[NO]

    k_prep<<<(B_ROWS + NTHREADS - 1) / NTHREADS, NTHREADS>>>(z, px_r, theta);
    k_sort<<<1, NTHREADS>>>();

    size_t smem = (size_t)(TILE_B * NL + NL * CHUNK_O) * sizeof(float);  // 49152 B
    k_gemm<<<dim3(MAX_TILES, NO / TILE_O), NTHREADS, smem>>>(z, W, S, offsets, sf, out);
}